// round 16
// baseline (speedup 1.0000x reference)
#include <cuda_runtime.h>
#include <cuda_fp16.h>
#include <cstdint>

#define BB 4
#define CH 1024
#define HH 50
#define WW 50
#define KK 512
#define NPIX (HH*WW)              // 2500
#define GPTS 8

// NHWC-transposed features in fp16: [B][H][W][C]  (20.5 MB scratch)
__device__ __align__(16) __half FT[BB * HH * WW * CH];

__device__ __forceinline__ uint32_t smem_u32(const void* p) {
    uint32_t a;
    asm("{ .reg .u64 t; cvta.to.shared.u64 t, %1; cvt.u32.u64 %0, t; }"
        : "=r"(a) : "l"(p));
    return a;
}
#define MBAR_INIT(a, c) \
    asm volatile("mbarrier.init.shared.b64 [%0], %1;" :: "r"(a), "r"(c) : "memory")
#define MBAR_EXPECT_TX(a, b) \
    asm volatile("mbarrier.arrive.expect_tx.shared.b64 _, [%0], %1;" :: "r"(a), "r"(b) : "memory")
#define BULK_CP(dst, src, n, mbar) \
    asm volatile("cp.async.bulk.shared::cta.global.mbarrier::complete_tx::bytes [%0], [%1], %2, [%3];" \
                 :: "r"(dst), "l"(src), "r"(n), "r"(mbar) : "memory")
#define MBAR_WAIT(mbar, parity) do {                                         \
    asm volatile(                                                            \
        "{\n\t.reg .pred P;\n\t"                                             \
        "WAIT_%=:\n\t"                                                       \
        "mbarrier.try_wait.parity.acquire.cta.shared::cta.b64 P, [%0], %1, 0x989680;\n\t" \
        "@P bra.uni DONE_%=;\n\t"                                            \
        "bra.uni WAIT_%=;\n\t"                                               \
        "DONE_%=:\n\t}"                                                      \
        :: "r"(mbar), "r"(parity) : "memory");                               \
} while (0)

// ---------------------------------------------------------------------------
// Kernel 1: NCHW fp32 -> NHWC fp16 transpose-convert (measured ~12us)
// ---------------------------------------------------------------------------
__global__ __launch_bounds__(256)
void transpose_kernel(const float* __restrict__ f) {
    __shared__ __align__(16) float tile[32][133];
    const int b  = blockIdx.z;
    const int p0 = blockIdx.x * 128;
    const int c0 = blockIdx.y * 32;
    const int t  = threadIdx.x;

    const float* fb = f + (size_t)b * CH * NPIX + (size_t)c0 * NPIX;
    #pragma unroll
    for (int j = 0; j < 4; j++) {
        int idx = t + j * 256;
        int c = idx >> 5;
        int q = idx & 31;
        int p = p0 + 4 * q;
        float4 v = make_float4(0.f, 0.f, 0.f, 0.f);
        if (p < NPIX) v = *(const float4*)(fb + (size_t)c * NPIX + p);
        tile[c][4 * q + 0] = v.x;
        tile[c][4 * q + 1] = v.y;
        tile[c][4 * q + 2] = v.z;
        tile[c][4 * q + 3] = v.w;
    }
    __syncthreads();

    __half* ob = FT + (size_t)b * NPIX * CH + c0;
    #pragma unroll
    for (int j = 0; j < 2; j++) {
        int idx = t + j * 256;
        int p = idx >> 2;
        int g = idx & 3;
        if (p0 + p < NPIX) {
            __half2 h0 = __floats2half2_rn(tile[8*g + 0][p], tile[8*g + 1][p]);
            __half2 h1 = __floats2half2_rn(tile[8*g + 2][p], tile[8*g + 3][p]);
            __half2 h2 = __floats2half2_rn(tile[8*g + 4][p], tile[8*g + 5][p]);
            __half2 h3 = __floats2half2_rn(tile[8*g + 6][p], tile[8*g + 7][p]);
            uint4 v;
            v.x = *(const unsigned int*)&h0;
            v.y = *(const unsigned int*)&h1;
            v.z = *(const unsigned int*)&h2;
            v.w = *(const unsigned int*)&h3;
            *(uint4*)(ob + (size_t)(p0 + p) * CH + 8 * g) = v;
        }
    }
}

// ---------------------------------------------------------------------------
// Kernel 2: fused RoIAlign + 2x2 avg pool — bulk-TMA gather (R15 + race fix).
// Grid (K,2): 512 ch/CTA, 256 threads, 2 ch/thread.
// Per grid row: thread 0 issues 32 x 1KB cp.async.bulk into the row buffer;
// completion via mbarrier expect_tx. Double-buffered.
// FIX vs R15: __syncthreads() between weight-table write and mainloop
// (in R14 the loop's own barrier provided this ordering; R15's MBAR_WAIT
// did not).
// Compute: packed fp16 bilinear (HMUL2/HFMA2) + fp32 accumulate.
// Drain: 4-chunk staged float4 stores (staging aliases buffer 0).
// ---------------------------------------------------------------------------
#define TB_BYTES 32768            // one tap buffer: 32 segs x 1KB

extern __shared__ __align__(16) unsigned char dynsmem[];   // 2*TB_BYTES

__global__ __launch_bounds__(256, 2)
void roi_pool_kernel(const float* __restrict__ rois, float* __restrict__ out) {
    const int k     = blockIdx.x;
    const int chunk = blockIdx.y;          // channel half
    const int tid   = threadIdx.x;

    __shared__ __align__(16) __half2 s_wh[GPTS][GPTS][4];  // dup'd fp16 weights
    __shared__ __align__(8) unsigned long long s_mbar[2];  // full barriers
    __shared__ float s_wx[GPTS], s_wy[GPTS], s_vx[GPTS], s_vy[GPTS];
    __shared__ int   s_x0[GPTS], s_y0[GPTS];
    __shared__ int   s_b;

    if (tid < GPTS) {
        float x1 = __ldg(&rois[k * 5 + 1]) * 0.0625f;
        float y1 = __ldg(&rois[k * 5 + 2]) * 0.0625f;
        float x2 = __ldg(&rois[k * 5 + 3]) * 0.0625f;
        float y2 = __ldg(&rois[k * 5 + 4]) * 0.0625f;
        float bh = fmaxf(y2 - y1, 0.0f) * (1.0f / 7.0f);
        float bw = fmaxf(x2 - x1, 0.0f) * (1.0f / 7.0f);
        float xv = x1 + (float)tid * bw;
        float yv = y1 + (float)tid * bh;
        s_vx[tid] = (xv >= 0.0f && xv < (float)WW) ? 1.0f : 0.0f;
        s_vy[tid] = (yv >= 0.0f && yv < (float)HH) ? 1.0f : 0.0f;
        int x0 = (int)floorf(xv);  x0 = min(max(x0, 0), WW - 2);
        int y0 = (int)floorf(yv);  y0 = min(max(y0, 0), HH - 2);
        s_x0[tid] = x0;  s_y0[tid] = y0;
        s_wx[tid] = xv - (float)x0;
        s_wy[tid] = yv - (float)y0;
        if (tid == 0) s_b = (int)__ldg(&rois[k * 5 + 0]);
    }
    const uint32_t mb0 = smem_u32(&s_mbar[0]);
    const uint32_t mb1 = smem_u32(&s_mbar[1]);
    if (tid == 0) { MBAR_INIT(mb0, 1); MBAR_INIT(mb1, 1); }
    __syncthreads();

    const uint32_t tb0 = smem_u32(dynsmem);
    const __half* base = FT + (size_t)s_b * (NPIX * CH) + chunk * 512;

    // thread 0 gathers one grid row (32 x 1KB bulk copies) into buffer bi
    #define GATHER(gy, bi)                                                   \
        do {                                                                 \
            uint32_t mb = (bi) ? mb1 : mb0;                                  \
            MBAR_EXPECT_TX(mb, TB_BYTES);                                    \
            const __half* r0 = base + (size_t)s_y0[gy] * (WW * CH);          \
            uint32_t sb = tb0 + (bi) * TB_BYTES;                             \
            _Pragma("unroll")                                                \
            for (int t = 0; t < 4; t++) {                                    \
                const __half* rt = r0 + (t >> 1) * (WW * CH) + (t & 1) * CH; \
                _Pragma("unroll")                                            \
                for (int gx = 0; gx < GPTS; gx++)                            \
                    BULK_CP(sb + (gx * 4 + t) * 1024,                        \
                            rt + s_x0[gx] * CH, 1024, mb);                   \
            }                                                                \
        } while (0)

    if (tid == 0) { GATHER(0, 0); GATHER(1, 1); }   // prologue

    // folded fp16 weights (overlaps in-flight TMA)
    if (tid < 64) {
        int gy = tid >> 3, gx = tid & 7;
        float wy = s_wy[gy], wx = s_wx[gx];
        float sc = 0.25f * s_vy[gy] * s_vx[gx];
        s_wh[gy][gx][0] = __float2half2_rn((1.0f - wy) * (1.0f - wx) * sc);
        s_wh[gy][gx][1] = __float2half2_rn((1.0f - wy) * wx * sc);
        s_wh[gy][gx][2] = __float2half2_rn(wy * (1.0f - wx) * sc);
        s_wh[gy][gx][3] = __float2half2_rn(wy * wx * sc);
    }
    __syncthreads();                       // *** FIX: weights visible to all

    float2 acc[49];
    #pragma unroll
    for (int i = 0; i < 49; i++) { acc[i].x = 0.0f; acc[i].y = 0.0f; }

    #pragma unroll
    for (int gy = 0; gy < GPTS; gy++) {
        MBAR_WAIT((gy & 1) ? mb1 : mb0, (gy >> 1) & 1);   // row gy landed

        const unsigned char* buf = dynsmem + (gy & 1) * TB_BYTES;
        #pragma unroll
        for (int gx = 0; gx < GPTS; gx++) {
            const uint2 wraw  = *(const uint2*)&s_wh[gy][gx][0];
            const uint2 wraw2 = *(const uint2*)&s_wh[gy][gx][2];
            __half2 w0; { unsigned int u = wraw.x;  w0 = *(const __half2*)&u; }
            __half2 w1; { unsigned int u = wraw.y;  w1 = *(const __half2*)&u; }
            __half2 w2; { unsigned int u = wraw2.x; w2 = *(const __half2*)&u; }
            __half2 w3; { unsigned int u = wraw2.y; w3 = *(const __half2*)&u; }

            const unsigned char* sp = buf + (gx * 4) * 1024 + tid * 4;
            __half2 v00 = *(const __half2*)(sp);
            __half2 v01 = *(const __half2*)(sp + 1024);
            __half2 v10 = *(const __half2*)(sp + 2048);
            __half2 v11 = *(const __half2*)(sp + 3072);

            __half2 cur = __hmul2(v00, w0);
            cur = __hfma2(v01, w1, cur);
            cur = __hfma2(v10, w2, cur);
            cur = __hfma2(v11, w3, cur);
            float2 cf = __half22float2(cur);

            if (gy >= 1 && gx >= 1) { acc[(gy-1)*7 + (gx-1)].x += cf.x; acc[(gy-1)*7 + (gx-1)].y += cf.y; }
            if (gy >= 1 && gx <  7) { acc[(gy-1)*7 +  gx   ].x += cf.x; acc[(gy-1)*7 +  gx   ].y += cf.y; }
            if (gy <  7 && gx >= 1) { acc[ gy   *7 + (gx-1)].x += cf.x; acc[ gy   *7 + (gx-1)].y += cf.y; }
            if (gy <  7 && gx <  7) { acc[ gy   *7 +  gx   ].x += cf.x; acc[ gy   *7 +  gx   ].y += cf.y; }
        }
        __syncthreads();                 // all readers done with buf[gy&1]
        if (tid == 0 && gy + 2 < GPTS) GATHER(gy + 2, gy & 1);
    }
    #undef GATHER

    // ---- staged, coalesced output writes (staging aliases buffer 0) ----
    float* sbuf = (float*)dynsmem;       // 25088 B < TB_BYTES
    float* outk = out + (size_t)k * (CH * 49) + (size_t)chunk * (512 * 49);
    #pragma unroll
    for (int sub = 0; sub < 4; sub++) {
        if ((tid >> 6) == sub) {
            int cl = tid * 2 - sub * 128;
            #pragma unroll
            for (int i = 0; i < 49; i++) {
                sbuf[(cl    ) * 49 + i] = acc[i].x;
                sbuf[(cl + 1) * 49 + i] = acc[i].y;
            }
        }
        __syncthreads();
        const float4* s4 = (const float4*)sbuf;
        float4* o4 = (float4*)(outk + sub * 6272);
        #pragma unroll
        for (int j = 0; j < 7; j++) {
            int i = tid + j * 256;
            if (i < 1568) o4[i] = s4[i];
        }
        __syncthreads();
    }
}

// ---------------------------------------------------------------------------
extern "C" void kernel_launch(void* const* d_in, const int* in_sizes, int n_in,
                              void* d_out, int out_size) {
    const float* features = (const float*)d_in[0];
    const float* rois     = (const float*)d_in[1];
    float* out            = (float*)d_out;

    const int smem = 2 * TB_BYTES;       // 64 KB
    static int done = 0;
    if (!done) {
        cudaFuncSetAttribute(roi_pool_kernel,
                             cudaFuncAttributeMaxDynamicSharedMemorySize, smem);
        done = 1;
    }

    dim3 tgrid((NPIX + 127) / 128, CH / 32, BB);   // (20, 32, 4)
    transpose_kernel<<<tgrid, 256>>>(features);
    roi_pool_kernel<<<dim3(KK, 2), 256, smem>>>(rois, out);
}

// round 17
// speedup vs baseline: 1.4581x; 1.4581x over previous
#include <cuda_runtime.h>
#include <cuda_fp16.h>
#include <cstdint>

#define BB 4
#define CH 1024
#define HH 50
#define WW 50
#define KK 512
#define NPIX (HH*WW)              // 2500
#define GPTS 8

// NHWC-transposed features in fp16: [B][H][W][C]  (20.5 MB scratch)
__device__ __align__(16) __half FT[BB * HH * WW * CH];

__device__ __forceinline__ uint32_t smem_u32(const void* p) {
    uint32_t a;
    asm("{ .reg .u64 t; cvta.to.shared.u64 t, %1; cvt.u32.u64 %0, t; }"
        : "=r"(a) : "l"(p));
    return a;
}
#define CP_ASYNC16(s, g) \
    asm volatile("cp.async.ca.shared.global [%0], [%1], 16;" :: "r"(s), "l"(g))
template<int N> __device__ __forceinline__ void cp_wait() {
    asm volatile("cp.async.wait_group %0;" :: "n"(N));
}
__device__ __forceinline__ void cp_commit() {
    asm volatile("cp.async.commit_group;");
}

// ---------------------------------------------------------------------------
// Kernel 1: NCHW fp32 -> NHWC fp16 transpose-convert (measured ~12us)
// ---------------------------------------------------------------------------
__global__ __launch_bounds__(256)
void transpose_kernel(const float* __restrict__ f) {
    __shared__ __align__(16) float tile[32][133];
    const int b  = blockIdx.z;
    const int p0 = blockIdx.x * 128;
    const int c0 = blockIdx.y * 32;
    const int t  = threadIdx.x;

    const float* fb = f + (size_t)b * CH * NPIX + (size_t)c0 * NPIX;
    #pragma unroll
    for (int j = 0; j < 4; j++) {
        int idx = t + j * 256;
        int c = idx >> 5;
        int q = idx & 31;
        int p = p0 + 4 * q;
        float4 v = make_float4(0.f, 0.f, 0.f, 0.f);
        if (p < NPIX) v = *(const float4*)(fb + (size_t)c * NPIX + p);
        tile[c][4 * q + 0] = v.x;
        tile[c][4 * q + 1] = v.y;
        tile[c][4 * q + 2] = v.z;
        tile[c][4 * q + 3] = v.w;
    }
    __syncthreads();

    __half* ob = FT + (size_t)b * NPIX * CH + c0;
    #pragma unroll
    for (int j = 0; j < 2; j++) {
        int idx = t + j * 256;
        int p = idx >> 2;
        int g = idx & 3;
        if (p0 + p < NPIX) {
            __half2 h0 = __floats2half2_rn(tile[8*g + 0][p], tile[8*g + 1][p]);
            __half2 h1 = __floats2half2_rn(tile[8*g + 2][p], tile[8*g + 3][p]);
            __half2 h2 = __floats2half2_rn(tile[8*g + 4][p], tile[8*g + 5][p]);
            __half2 h3 = __floats2half2_rn(tile[8*g + 6][p], tile[8*g + 7][p]);
            uint4 v;
            v.x = *(const unsigned int*)&h0;
            v.y = *(const unsigned int*)&h1;
            v.z = *(const unsigned int*)&h2;
            v.w = *(const unsigned int*)&h3;
            *(uint4*)(ob + (size_t)(p0 + p) * CH + 8 * g) = v;
        }
    }
}

// ---------------------------------------------------------------------------
// Kernel 2: fused RoIAlign + 2x2 avg pool — R14 frame + fp16 rowsum regs.
// Grid (K,2): 512 ch/CTA, 256 threads, 2 ch/thread.
// cp.async taps double-buffered, 2 barriers/row (EXACT R14 cadence).
// Mainloop per gx: 4 LDS + HMUL2/3xHFMA2 + 1 HADD2 (rowsum into rs[gy][*]).
// Pooled combine rs[py]+rs[py+1] + fp32 convert happens in the drain.
// rs = 56 half2 regs -> ~85 regs -> 3 CTAs/SM.
// ---------------------------------------------------------------------------
#define TB_BYTES 32768            // one tap buffer: 32 segs x 1KB

extern __shared__ __align__(16) unsigned char dynsmem[];   // 2*TB_BYTES

__global__ __launch_bounds__(256, 3)
void roi_pool_kernel(const float* __restrict__ rois, float* __restrict__ out) {
    const int k     = blockIdx.x;
    const int chunk = blockIdx.y;          // channel half
    const int tid   = threadIdx.x;

    __shared__ __align__(16) __half2 s_wh[GPTS][GPTS][4];  // dup'd fp16 weights
    __shared__ float s_wx[GPTS], s_wy[GPTS], s_vx[GPTS], s_vy[GPTS];
    __shared__ int   s_x0[GPTS], s_y0[GPTS];
    __shared__ int   s_b;

    if (tid < GPTS) {
        float x1 = __ldg(&rois[k * 5 + 1]) * 0.0625f;
        float y1 = __ldg(&rois[k * 5 + 2]) * 0.0625f;
        float x2 = __ldg(&rois[k * 5 + 3]) * 0.0625f;
        float y2 = __ldg(&rois[k * 5 + 4]) * 0.0625f;
        float bh = fmaxf(y2 - y1, 0.0f) * (1.0f / 7.0f);
        float bw = fmaxf(x2 - x1, 0.0f) * (1.0f / 7.0f);
        float xv = x1 + (float)tid * bw;
        float yv = y1 + (float)tid * bh;
        s_vx[tid] = (xv >= 0.0f && xv < (float)WW) ? 1.0f : 0.0f;
        s_vy[tid] = (yv >= 0.0f && yv < (float)HH) ? 1.0f : 0.0f;
        int x0 = (int)floorf(xv);  x0 = min(max(x0, 0), WW - 2);
        int y0 = (int)floorf(yv);  y0 = min(max(y0, 0), HH - 2);
        s_x0[tid] = x0;  s_y0[tid] = y0;
        s_wx[tid] = xv - (float)x0;
        s_wy[tid] = yv - (float)y0;
        if (tid == 0) s_b = (int)__ldg(&rois[k * 5 + 0]);
    }
    __syncthreads();

    if (tid < 64) {
        int gy = tid >> 3, gx = tid & 7;
        float wy = s_wy[gy], wx = s_wx[gx];
        float sc = 0.25f * s_vy[gy] * s_vx[gx];
        s_wh[gy][gx][0] = __float2half2_rn((1.0f - wy) * (1.0f - wx) * sc);
        s_wh[gy][gx][1] = __float2half2_rn((1.0f - wy) * wx * sc);
        s_wh[gy][gx][2] = __float2half2_rn(wy * (1.0f - wx) * sc);
        s_wh[gy][gx][3] = __float2half2_rn(wy * wx * sc);
    }

    // gather role: t4 = tap, col = 16B chunk within 1KB segment
    const int t4  = tid >> 6;
    const int dy  = t4 >> 1, dx = t4 & 1;
    const int col = tid & 63;
    const __half* bbase = FT + (size_t)s_b * (NPIX * CH) + chunk * 512
                             + (size_t)dx * CH + col * 8;
    int xoff[GPTS];
    #pragma unroll
    for (int gx = 0; gx < GPTS; gx++) xoff[gx] = s_x0[gx] * CH;

    const uint32_t tb0 = smem_u32(dynsmem);
    const uint32_t smy = tb0 + (t4 * 1024 + col * 16);

    #define GATHER(gy, bi)                                                  \
        do {                                                                \
            const __half* rb = bbase + (size_t)(s_y0[gy] + dy) * (WW * CH); \
            uint32_t sb = smy + (bi) * TB_BYTES;                            \
            _Pragma("unroll")                                               \
            for (int j = 0; j < 8; j++)                                     \
                CP_ASYNC16(sb + j * 4096, rb + xoff[j]);                    \
            cp_commit();                                                    \
        } while (0)

    GATHER(0, 0);                          // prologue

    __half2 rs[GPTS][7];                   // per-grid-row rowsums (fp16)

    #pragma unroll
    for (int gy = 0; gy < GPTS; gy++) {
        if (gy < GPTS - 1) GATHER(gy + 1, (gy + 1) & 1);
        if (gy < GPTS - 1) cp_wait<1>(); else cp_wait<0>();
        __syncthreads();                   // row-gy taps visible (+weights on gy=0)

        const unsigned char* buf = dynsmem + (gy & 1) * TB_BYTES;
        __half2 cprev;
        #pragma unroll
        for (int gx = 0; gx < GPTS; gx++) {
            const uint2 wraw  = *(const uint2*)&s_wh[gy][gx][0];
            const uint2 wraw2 = *(const uint2*)&s_wh[gy][gx][2];
            __half2 w0; { unsigned int u = wraw.x;  w0 = *(const __half2*)&u; }
            __half2 w1; { unsigned int u = wraw.y;  w1 = *(const __half2*)&u; }
            __half2 w2; { unsigned int u = wraw2.x; w2 = *(const __half2*)&u; }
            __half2 w3; { unsigned int u = wraw2.y; w3 = *(const __half2*)&u; }

            const unsigned char* sp = buf + (gx * 4) * 1024 + tid * 4;
            __half2 v00 = *(const __half2*)(sp);
            __half2 v01 = *(const __half2*)(sp + 1024);
            __half2 v10 = *(const __half2*)(sp + 2048);
            __half2 v11 = *(const __half2*)(sp + 3072);

            __half2 cur = __hmul2(v00, w0);
            cur = __hfma2(v01, w1, cur);
            cur = __hfma2(v10, w2, cur);
            cur = __hfma2(v11, w3, cur);

            if (gx > 0) rs[gy][gx - 1] = __hadd2(cprev, cur);
            cprev = cur;
        }
        __syncthreads();                   // done reading buf before refill
    }
    #undef GATHER

    // ---- staged, coalesced output writes (staging aliases buffer 0) ----
    // pooled[py][px] = rs[py][px] + rs[py+1][px], converted to fp32 on the fly
    float* sbuf = (float*)dynsmem;         // 25088 B < TB_BYTES
    float* outk = out + (size_t)k * (CH * 49) + (size_t)chunk * (512 * 49);
    #pragma unroll
    for (int sub = 0; sub < 4; sub++) {
        if ((tid >> 6) == sub) {
            int cl = tid * 2 - sub * 128;
            #pragma unroll
            for (int py = 0; py < 7; py++) {
                #pragma unroll
                for (int px = 0; px < 7; px++) {
                    __half2 s = __hadd2(rs[py][px], rs[py + 1][px]);
                    float2 cf = __half22float2(s);
                    sbuf[(cl    ) * 49 + py * 7 + px] = cf.x;
                    sbuf[(cl + 1) * 49 + py * 7 + px] = cf.y;
                }
            }
        }
        __syncthreads();
        const float4* s4 = (const float4*)sbuf;
        float4* o4 = (float4*)(outk + sub * 6272);
        #pragma unroll
        for (int j = 0; j < 7; j++) {
            int i = tid + j * 256;
            if (i < 1568) o4[i] = s4[i];
        }
        __syncthreads();
    }
}

// ---------------------------------------------------------------------------
extern "C" void kernel_launch(void* const* d_in, const int* in_sizes, int n_in,
                              void* d_out, int out_size) {
    const float* features = (const float*)d_in[0];
    const float* rois     = (const float*)d_in[1];
    float* out            = (float*)d_out;

    const int smem = 2 * TB_BYTES;         // 64 KB
    static int done = 0;
    if (!done) {
        cudaFuncSetAttribute(roi_pool_kernel,
                             cudaFuncAttributeMaxDynamicSharedMemorySize, smem);
        done = 1;
    }

    dim3 tgrid((NPIX + 127) / 128, CH / 32, BB);   // (20, 32, 4)
    transpose_kernel<<<tgrid, 256>>>(features);
    roi_pool_kernel<<<dim3(KK, 2), 256, smem>>>(rois, out);
}